// round 10
// baseline (speedup 1.0000x reference)
#include <cuda_runtime.h>
#include <cuda_bf16.h>
#include <cuda_fp16.h>
#include <cstdint>

#define Nn 100000
#define Ee 1600000
#define Hh 128
#define Gg 64
#define EPSf 1e-5f

#define SCAN_BS 1024
#define NBLK ((Nn + SCAN_BS - 1) / SCAN_BS)   // 98
#define BN_REP 4
#define TILES ((Nn + 255) / 256)              // 391

// ---------------- mma GEMM smem layout (256 rows per tile) ----------------
#define Pp 136                        // bf16 elements per row (272 B, stride 68 words)
#define AIMG_B (256 * Pp * 2)         // 69632 B per A image
#define WIMG_B (128 * Pp * 2)         // 34816 B per W image
#define SM_AHI 0
#define SM_ALO AIMG_B
#define SM_W   (2 * AIMG_B)
#define SM_BN  (2 * AIMG_B + 2 * WIMG_B)
#define SM_TOTAL (SM_BN + 1024)       // 209920 B

#define MMA_BF16(d, a, b0, b1) \
    asm volatile("mma.sync.aligned.m16n8k16.row.col.f32.bf16.bf16.f32 " \
        "{%0,%1,%2,%3}, {%4,%5,%6,%7}, {%8,%9}, {%0,%1,%2,%3};" \
        : "+f"((d)[0]), "+f"((d)[1]), "+f"((d)[2]), "+f"((d)[3]) \
        : "r"((a)[0]), "r"((a)[1]), "r"((a)[2]), "r"((a)[3]), "r"(b0), "r"(b1))

#define LDSM_X4(r0, r1, r2, r3, addr) \
    asm volatile("ldmatrix.sync.aligned.m8n8.x4.shared.b16 {%0,%1,%2,%3}, [%4];" \
        : "=r"(r0), "=r"(r1), "=r"(r2), "=r"(r3) : "r"(addr))

// ---------------- device scratch ----------------
struct ZBlob {                         // zeroed with one memset per call
    int   deg[Nn];
    int   cursor[Nn];
    float bnsum[3][BN_REP][2 * Hh];
    float xsum[Gg * Hh];
    float cnt[Gg];
};
__device__ ZBlob g_z;
__device__ float g_dinv[Nn];
__device__ int   g_off[Nn + 1];
__device__ int   g_bsum[SCAN_BS];
__device__ int2  g_csr[Ee];                       // {src, weight}
__device__ __half g_h16[(size_t)Nn * Hh];         // raw A @ W, fp16
__device__ float g_agg[(size_t)Nn * Hh];
__device__ float g_act[(size_t)Nn * Hh];
__device__ __nv_bfloat16 g_wt[3][2][128 * Pp];    // padded W^T bf16 hi/lo images

__device__ __forceinline__ uint32_t smem_to_u32(const void* p) {
    uint32_t a;
    asm("{ .reg .u64 t; cvta.to.shared.u64 t, %1; cvt.u32.u64 %0, t; }" : "=r"(a) : "l"(p));
    return a;
}

// ---------------- degree ----------------
__global__ void k_deg(const int* __restrict__ dst) {
    int e = blockIdx.x * blockDim.x + threadIdx.x;
    if (e < Ee) atomicAdd(&g_z.deg[dst[e]], 1);
}

// ---- W split: fp32 W[k][n] -> padded bf16 hi/lo images of W^T[n][k] ----
__global__ void k_wsplit(const float* __restrict__ W1, const float* __restrict__ W2,
                         const float* __restrict__ W3) {
    int layer = blockIdx.y;
    const float* Ws = (layer == 0) ? W1 : (layer == 1) ? W2 : W3;
    int n = blockIdx.x;
    int k = threadIdx.x;
    float v = Ws[k * 128 + n];
    __nv_bfloat16 hi = __float2bfloat16(v);
    float lo = v - __bfloat162float(hi);
    g_wt[layer][0][n * Pp + k] = hi;
    g_wt[layer][1][n * Pp + k] = __float2bfloat16(lo);
}

// ---------------- exclusive scan of degrees -> CSR offsets ----------------
__global__ void k_scan1() {
    __shared__ int s[SCAN_BS];
    int tid = threadIdx.x;
    int i = blockIdx.x * SCAN_BS + tid;
    int v = (i < Nn) ? g_z.deg[i] : 0;
    s[tid] = v;
    __syncthreads();
    for (int d = 1; d < SCAN_BS; d <<= 1) {
        int t = (tid >= d) ? s[tid - d] : 0;
        __syncthreads();
        s[tid] += t;
        __syncthreads();
    }
    if (i < Nn) g_off[i] = s[tid] - v;
    if (tid == SCAN_BS - 1) g_bsum[blockIdx.x] = s[tid];
}

__global__ void k_scan2() {
    __shared__ int s[128];
    int tid = threadIdx.x;
    int v = (tid < NBLK) ? g_bsum[tid] : 0;
    s[tid] = v;
    __syncthreads();
    for (int d = 1; d < 128; d <<= 1) {
        int t = (tid >= d) ? s[tid - d] : 0;
        __syncthreads();
        s[tid] += t;
        __syncthreads();
    }
    g_bsum[tid] = s[tid] - v;
}

__global__ void k_scan3() {   // + dinv
    int i = blockIdx.x * blockDim.x + threadIdx.x;
    if (i < Nn) {
        g_off[i] += g_bsum[i >> 10];
        g_dinv[i] = rsqrtf((float)g_z.deg[i] + 1.0f);
    }
    if (i == 0) g_off[Nn] = Ee;
}

__global__ void k_fill(const int* __restrict__ src, const int* __restrict__ dst) {
    int e = blockIdx.x * blockDim.x + threadIdx.x;
    if (e >= Ee) return;
    int d = dst[e];
    int s = src[e];
    int pos = g_off[d] + atomicAdd(&g_z.cursor[d], 1);
    g_csr[pos] = make_int2(s, __float_as_int(g_dinv[s] * g_dinv[d]));
}

// ---- tensor GEMM: g_h16[M,128] = fp16( A @ W ), ldmatrix frags, grid=TILES ----
// mode 0: A = Ain; mode 1: A = relu(bn(g_agg)) -> also g_act;
// mode 2: A = relu(bn(g_agg)) + g_act -> also g_act
__global__ __launch_bounds__(512)
void gemm_tc(const float* __restrict__ Ain, int layer, int mode, int bnidx,
             const float* __restrict__ gam, const float* __restrict__ bet) {
    extern __shared__ char sm[];
    float* s_bn = (float*)(sm + SM_BN);
    uint32_t smb = smem_to_u32(sm);
    int tid = threadIdx.x;
    int wid = tid >> 5;
    int lane = tid & 31;
    int gid = lane >> 2;
    int tig = lane & 3;
    int row0 = blockIdx.x * 256;

    // W hi+lo images -> smem
    {
        const uint4* wsrc = (const uint4*)(&g_wt[layer][0][0]);
        uint4* wdst = (uint4*)(sm + SM_W);
        for (int i = tid; i < 4352; i += 512) wdst[i] = wsrc[i];
    }
    // BN scale/shift
    if (mode && tid < 128) {
        float s = 0.f, q = 0.f;
#pragma unroll
        for (int r = 0; r < BN_REP; r++) {
            s += g_z.bnsum[bnidx][r][tid];
            q += g_z.bnsum[bnidx][r][128 + tid];
        }
        float mean = s * (1.0f / (float)Nn);
        float var = q * (1.0f / (float)Nn) - mean * mean;
        float sc = gam[tid] * rsqrtf(var + EPSf);
        s_bn[tid] = sc;
        s_bn[128 + tid] = bet[tid] - mean * sc;
    }
    __syncthreads();

    // A prologue: 512 threads cover 256 rows x 2 halves
    {
        int r = tid & 255;
        int half = tid >> 8;
        int gr = row0 + r;
#pragma unroll
        for (int j = 0; j < 8; j++) {
            int k0 = half * 64 + j * 8;
            float4 va = make_float4(0.f, 0.f, 0.f, 0.f), vb = va;
            if (gr < Nn) {
                if (mode == 0) {
                    const float4* ap = (const float4*)(Ain + (size_t)gr * 128 + k0);
                    va = ap[0]; vb = ap[1];
                } else {
                    const float4* ap = (const float4*)(g_agg + (size_t)gr * 128 + k0);
                    float4 a0 = ap[0], a1 = ap[1];
                    const float4* scp = (const float4*)(s_bn + k0);
                    const float4* shp = (const float4*)(s_bn + 128 + k0);
                    float4 s0 = scp[0], s1 = scp[1], h0 = shp[0], h1 = shp[1];
                    va.x = fmaxf(fmaf(a0.x, s0.x, h0.x), 0.f);
                    va.y = fmaxf(fmaf(a0.y, s0.y, h0.y), 0.f);
                    va.z = fmaxf(fmaf(a0.z, s0.z, h0.z), 0.f);
                    va.w = fmaxf(fmaf(a0.w, s0.w, h0.w), 0.f);
                    vb.x = fmaxf(fmaf(a1.x, s1.x, h1.x), 0.f);
                    vb.y = fmaxf(fmaf(a1.y, s1.y, h1.y), 0.f);
                    vb.z = fmaxf(fmaf(a1.z, s1.z, h1.z), 0.f);
                    vb.w = fmaxf(fmaf(a1.w, s1.w, h1.w), 0.f);
                    if (mode == 2) {
                        const float4* rp = (const float4*)(g_act + (size_t)gr * 128 + k0);
                        float4 r0 = rp[0], r1 = rp[1];
                        va.x += r0.x; va.y += r0.y; va.z += r0.z; va.w += r0.w;
                        vb.x += r1.x; vb.y += r1.y; vb.z += r1.z; vb.w += r1.w;
                    }
                    float4* op = (float4*)(g_act + (size_t)gr * 128 + k0);
                    op[0] = va; op[1] = vb;
                }
            }
            float vv[8] = {va.x, va.y, va.z, va.w, vb.x, vb.y, vb.z, vb.w};
            uint32_t hw[4], lw[4];
#pragma unroll
            for (int q = 0; q < 4; q++) {
                __nv_bfloat162 hb = __floats2bfloat162_rn(vv[2 * q], vv[2 * q + 1]);
                float ra = __bfloat162float(hb.x), rb = __bfloat162float(hb.y);
                __nv_bfloat162 lb = __floats2bfloat162_rn(vv[2 * q] - ra, vv[2 * q + 1] - rb);
                hw[q] = *(uint32_t*)&hb;
                lw[q] = *(uint32_t*)&lb;
            }
            size_t off = ((size_t)r * Pp + k0) * 2;
            *(uint4*)(sm + SM_AHI + off) = make_uint4(hw[0], hw[1], hw[2], hw[3]);
            *(uint4*)(sm + SM_ALO + off) = make_uint4(lw[0], lw[1], lw[2], lw[3]);
        }
    }
    __syncthreads();

    // warp tile: 32 rows x 64 cols
    int m0 = (wid >> 1) * 32;
    int nb = (wid & 1) * 64;

    uint32_t aAddr0 = smb + SM_AHI +
        ((uint32_t)((m0 + (lane & 15)) * Pp + ((lane >> 4) << 3)) << 1);
    uint32_t aAddr1 = aAddr0 + (uint32_t)(16 * Pp * 2);
    int brow = (lane & 7) | ((lane >> 4) << 3);
    uint32_t bAddr = smb + SM_W +
        ((uint32_t)((nb + brow) * Pp + (((lane >> 3) & 1) << 3)) << 1);

    float acc[2][8][4];
#pragma unroll
    for (int t = 0; t < 2; t++)
#pragma unroll
        for (int nt = 0; nt < 8; nt++) {
            acc[t][nt][0] = 0.f; acc[t][nt][1] = 0.f;
            acc[t][nt][2] = 0.f; acc[t][nt][3] = 0.f;
        }

#pragma unroll 2
    for (int kc = 0; kc < 8; kc++) {
        uint32_t koff = kc * 32;     // 16 bf16 = 32 bytes
        uint32_t ah[2][4], al[2][4];
        LDSM_X4(ah[0][0], ah[0][1], ah[0][2], ah[0][3], aAddr0 + koff);
        LDSM_X4(ah[1][0], ah[1][1], ah[1][2], ah[1][3], aAddr1 + koff);
        LDSM_X4(al[0][0], al[0][1], al[0][2], al[0][3], aAddr0 + AIMG_B + koff);
        LDSM_X4(al[1][0], al[1][1], al[1][2], al[1][3], aAddr1 + AIMG_B + koff);
#pragma unroll
        for (int p = 0; p < 4; p++) {
            uint32_t bAdr = bAddr + (uint32_t)(p * 16 * Pp * 2) + koff;
            uint32_t bh0, bh1, bh2, bh3, bl0, bl1, bl2, bl3;
            LDSM_X4(bh0, bh1, bh2, bh3, bAdr);
            LDSM_X4(bl0, bl1, bl2, bl3, bAdr + WIMG_B);
#pragma unroll
            for (int t = 0; t < 2; t++) {
                MMA_BF16(acc[t][2 * p],     ah[t], bh0, bh1);
                MMA_BF16(acc[t][2 * p],     ah[t], bl0, bl1);
                MMA_BF16(acc[t][2 * p],     al[t], bh0, bh1);
                MMA_BF16(acc[t][2 * p + 1], ah[t], bh2, bh3);
                MMA_BF16(acc[t][2 * p + 1], ah[t], bl2, bl3);
                MMA_BF16(acc[t][2 * p + 1], al[t], bh2, bh3);
            }
        }
    }

    // epilogue: fp16 store (raw product)
#pragma unroll
    for (int t = 0; t < 2; t++) {
        int r1 = row0 + m0 + t * 16 + gid;
        int r2 = r1 + 8;
#pragma unroll
        for (int nt = 0; nt < 8; nt++) {
            int c2 = (wid & 1) * 32 + nt * 4 + tig;
            if (r1 < Nn) {
                __half2 p = __floats2half2_rn(acc[t][nt][0], acc[t][nt][1]);
                ((uint32_t*)g_h16)[(size_t)r1 * 64 + c2] = *(uint32_t*)&p;
            }
            if (r2 < Nn) {
                __half2 p = __floats2half2_rn(acc[t][nt][2], acc[t][nt][3]);
                ((uint32_t*)g_h16)[(size_t)r2 * 64 + c2] = *(uint32_t*)&p;
            }
        }
    }
}

// ------- gather (fp16 payload, weighted, 4-deep MLP) + bias + BN stats -------
__global__ __launch_bounds__(512) void k_gather(const float* __restrict__ bias, int bnidx) {
    __shared__ float ss[16 * 128];

    int tid = threadIdx.x;
    int wloc = tid >> 5;
    int lane = tid & 31;
    int wid = blockIdx.x * 16 + wloc;

    int beg = g_off[wid];
    int end = g_off[wid + 1];
    float di = g_dinv[wid];
    float d2 = di * di;

    const uint2* hv = (const uint2*)g_h16;
    uint2 hs = hv[(size_t)wid * 32 + lane];
    float2 f0 = __half22float2(*(__half2*)&hs.x);
    float2 f1 = __half22float2(*(__half2*)&hs.y);
    float4 acc = make_float4(f0.x * d2, f0.y * d2, f1.x * d2, f1.y * d2);
    float4 acc2 = make_float4(0.f, 0.f, 0.f, 0.f);

    const int2* csr = g_csr;
    int e = beg;
    for (; e + 4 <= end; e += 4) {
        int2 c0 = csr[e];
        int2 c1 = csr[e + 1];
        int2 c2 = csr[e + 2];
        int2 c3 = csr[e + 3];
        uint2 v0 = hv[(size_t)c0.x * 32 + lane];
        uint2 v1 = hv[(size_t)c1.x * 32 + lane];
        uint2 v2 = hv[(size_t)c2.x * 32 + lane];
        uint2 v3 = hv[(size_t)c3.x * 32 + lane];
        float w0 = __int_as_float(c0.y), w1 = __int_as_float(c1.y);
        float w2 = __int_as_float(c2.y), w3 = __int_as_float(c3.y);
        float2 a0 = __half22float2(*(__half2*)&v0.x), a1 = __half22float2(*(__half2*)&v0.y);
        float2 b0 = __half22float2(*(__half2*)&v1.x), b1 = __half22float2(*(__half2*)&v1.y);
        float2 d0 = __half22float2(*(__half2*)&v2.x), d1 = __half22float2(*(__half2*)&v2.y);
        float2 e0 = __half22float2(*(__half2*)&v3.x), e1 = __half22float2(*(__half2*)&v3.y);
        acc.x = fmaf(a0.x, w0, acc.x);  acc.y = fmaf(a0.y, w0, acc.y);
        acc.z = fmaf(a1.x, w0, acc.z);  acc.w = fmaf(a1.y, w0, acc.w);
        acc2.x = fmaf(b0.x, w1, acc2.x); acc2.y = fmaf(b0.y, w1, acc2.y);
        acc2.z = fmaf(b1.x, w1, acc2.z); acc2.w = fmaf(b1.y, w1, acc2.w);
        acc.x = fmaf(d0.x, w2, acc.x);  acc.y = fmaf(d0.y, w2, acc.y);
        acc.z = fmaf(d1.x, w2, acc.z);  acc.w = fmaf(d1.y, w2, acc.w);
        acc2.x = fmaf(e0.x, w3, acc2.x); acc2.y = fmaf(e0.y, w3, acc2.y);
        acc2.z = fmaf(e1.x, w3, acc2.z); acc2.w = fmaf(e1.y, w3, acc2.w);
    }
    for (; e < end; e++) {
        int2 c0 = csr[e];
        uint2 v0 = hv[(size_t)c0.x * 32 + lane];
        float w0 = __int_as_float(c0.y);
        float2 a0 = __half22float2(*(__half2*)&v0.x);
        float2 a1 = __half22float2(*(__half2*)&v0.y);
        acc.x = fmaf(a0.x, w0, acc.x);
        acc.y = fmaf(a0.y, w0, acc.y);
        acc.z = fmaf(a1.x, w0, acc.z);
        acc.w = fmaf(a1.y, w0, acc.w);
    }
    acc.x += acc2.x; acc.y += acc2.y; acc.z += acc2.z; acc.w += acc2.w;

    float4 b4 = ((const float4*)bias)[lane];
    acc.x += b4.x; acc.y += b4.y; acc.z += b4.z; acc.w += b4.w;
    ((float4*)g_agg)[(size_t)wid * 32 + lane] = acc;

    int base = wloc * 128 + lane * 4;
    ss[base + 0] = acc.x; ss[base + 1] = acc.y; ss[base + 2] = acc.z; ss[base + 3] = acc.w;
    __syncthreads();

    if (tid < 256) {
        int c = tid & 127;
        int part = tid >> 7;
        float r = 0.f;
        if (part == 0) {
#pragma unroll
            for (int w = 0; w < 16; w++) r += ss[w * 128 + c];
        } else {
#pragma unroll
            for (int w = 0; w < 16; w++) { float v = ss[w * 128 + c]; r = fmaf(v, v, r); }
        }
        atomicAdd(&g_z.bnsum[bnidx][blockIdx.x & (BN_REP - 1)][part * 128 + c], r);
    }
}

// ---------------- pooling with fused layer-3 BN finalize+apply ----------------
#define PCHUNK 256
__global__ void k_pool(const int* __restrict__ batch,
                       const float* __restrict__ gam, const float* __restrict__ bet) {
    int c = threadIdx.x;
    float s = 0.f, q = 0.f;
#pragma unroll
    for (int r = 0; r < BN_REP; r++) {
        s += g_z.bnsum[2][r][c];
        q += g_z.bnsum[2][r][128 + c];
    }
    float mean = s * (1.0f / (float)Nn);
    float var = q * (1.0f / (float)Nn) - mean * mean;
    float sc = gam[c] * rsqrtf(var + EPSf);
    float sh = bet[c] - mean * sc;

    int start = blockIdx.x * PCHUNK;
    if (start >= Nn) return;
    int end = min(start + PCHUNK, Nn);
    float acc = 0.f, ccnt = 0.f;
    int gp = batch[start];
    for (int n = start; n < end; n++) {
        int g = batch[n];
        if (g != gp) {
            atomicAdd(&g_z.xsum[gp * 128 + c], acc);
            if (c == 0) atomicAdd(&g_z.cnt[gp], ccnt);
            acc = 0.f; ccnt = 0.f; gp = g;
        }
        float a = g_agg[(size_t)n * 128 + c];
        float v = fmaxf(fmaf(a, sc, sh), 0.f) + g_act[(size_t)n * 128 + c];
        acc += v;
        ccnt += 1.f;
    }
    atomicAdd(&g_z.xsum[gp * 128 + c], acc);
    if (c == 0) atomicAdd(&g_z.cnt[gp], ccnt);
}

// ---------------- MLP head ----------------
__global__ void k_mlp(const float* __restrict__ Wm1, const float* __restrict__ bm1,
                      const float* __restrict__ Wm2, const float* __restrict__ bm2,
                      float* __restrict__ out) {
    __shared__ float zs[128], zm[128], hid[128];
    int g = blockIdx.x, c = threadIdx.x;
    float cnt = fmaxf(g_z.cnt[g], 1.0f);
    float xs = g_z.xsum[g * 128 + c];
    zs[c] = xs;
    zm[c] = xs / cnt;
    __syncthreads();
    float acc = bm1[c];
#pragma unroll 8
    for (int k = 0; k < 128; k++)
        acc += zs[k] * Wm1[k * 128 + c] + zm[k] * Wm1[(128 + k) * 128 + c];
    hid[c] = fmaxf(acc, 0.f) * Wm2[c];
    __syncthreads();
    for (int s = 64; s > 0; s >>= 1) {
        if (c < s) hid[c] += hid[c + s];
        __syncthreads();
    }
    if (c == 0) out[g] = hid[0] + bm2[0];
}

// ---------------- host ----------------
extern "C" void kernel_launch(void* const* d_in, const int* in_sizes, int n_in,
                              void* d_out, int out_size) {
    const float *x, *W1, *b1, *W2, *b2, *W3, *b3;
    const float *g1, *be1, *g2, *be2, *g3, *be3;
    const float *Wm1, *bm1, *Wm2, *bm2;
    const int *ei, *batch;

    if (in_sizes[1] == 2 * Ee) {
        x   = (const float*)d_in[0];
        ei  = (const int*)  d_in[1];
        batch = (const int*)d_in[2];
        W1 = (const float*)d_in[3];  b1 = (const float*)d_in[4];
        W2 = (const float*)d_in[5];  b2 = (const float*)d_in[6];
        W3 = (const float*)d_in[7];  b3 = (const float*)d_in[8];
        g1 = (const float*)d_in[9];  be1 = (const float*)d_in[10];
        g2 = (const float*)d_in[11]; be2 = (const float*)d_in[12];
        g3 = (const float*)d_in[13]; be3 = (const float*)d_in[14];
        Wm1 = (const float*)d_in[15]; bm1 = (const float*)d_in[16];
        Wm2 = (const float*)d_in[17]; bm2 = (const float*)d_in[18];
    } else {
        x   = (const float*)d_in[0];
        W1 = (const float*)d_in[1];  b1 = (const float*)d_in[2];
        g1 = (const float*)d_in[3];  be1 = (const float*)d_in[4];
        W2 = (const float*)d_in[5];  b2 = (const float*)d_in[6];
        g2 = (const float*)d_in[7];  be2 = (const float*)d_in[8];
        W3 = (const float*)d_in[9];  b3 = (const float*)d_in[10];
        g3 = (const float*)d_in[11]; be3 = (const float*)d_in[12];
        Wm1 = (const float*)d_in[13]; bm1 = (const float*)d_in[14];
        Wm2 = (const float*)d_in[15]; bm2 = (const float*)d_in[16];
        ei  = (const int*)d_in[17];
        batch = (const int*)d_in[18];
    }

    const int* src = ei;
    const int* dst = ei + Ee;
    float* out = (float*)d_out;

    static cudaStream_t s_side = nullptr;
    static cudaEvent_t s_e1 = nullptr, s_e2 = nullptr;
    if (!s_side) {
        cudaStreamCreateWithFlags(&s_side, cudaStreamNonBlocking);
        cudaEventCreateWithFlags(&s_e1, cudaEventDisableTiming);
        cudaEventCreateWithFlags(&s_e2, cudaEventDisableTiming);
    }

    cudaFuncSetAttribute(gemm_tc, cudaFuncAttributeMaxDynamicSharedMemorySize, SM_TOTAL);

    const int ZB = (Nn + 255) / 256;          // 391
    const int EB = (Ee + 255) / 256;          // 6250
    const int GATB = (Nn + 15) / 16;          // 6250
    const int POOLB = (Nn + PCHUNK - 1) / PCHUNK;

    // zero scratch, fork CSR build onto side stream
    void* zptr = nullptr;
    cudaGetSymbolAddress(&zptr, g_z);
    cudaMemsetAsync(zptr, 0, sizeof(ZBlob), 0);
    cudaEventRecord(s_e1, 0);
    cudaStreamWaitEvent(s_side, s_e1, 0);

    // interleaved submission: gemm1 is the 4th kernel (profiling slot)
    k_deg<<<EB, 256, 0, s_side>>>(dst);                 // 1
    k_wsplit<<<dim3(128, 3), 128>>>(W1, W2, W3);        // 2 (main)
    k_scan1<<<NBLK, SCAN_BS, 0, s_side>>>();            // 3
    gemm_tc<<<TILES, 512, SM_TOTAL>>>(x, 0, 0, 0, nullptr, nullptr);   // 4 (main)
    k_scan2<<<1, 128, 0, s_side>>>();                   // 5
    k_scan3<<<ZB, 256, 0, s_side>>>();                  // 6
    k_fill<<<EB, 256, 0, s_side>>>(src, dst);           // 7
    cudaEventRecord(s_e2, s_side);
    cudaStreamWaitEvent(0, s_e2, 0);

    // layer 1 aggregate + BN stats
    k_gather<<<GATB, 512>>>(b1, 0);

    // layer 2
    gemm_tc<<<TILES, 512, SM_TOTAL>>>(nullptr, 1, 1, 0, g1, be1);
    k_gather<<<GATB, 512>>>(b2, 1);

    // layer 3
    gemm_tc<<<TILES, 512, SM_TOTAL>>>(nullptr, 2, 2, 1, g2, be2);
    k_gather<<<GATB, 512>>>(b3, 2);

    // pooling + MLP
    k_pool<<<POOLB, 128>>>(batch, g3, be3);
    k_mlp<<<Gg, 128>>>(Wm1, bm1, Wm2, bm2, out);
}

// round 11
// speedup vs baseline: 1.0079x; 1.0079x over previous
#include <cuda_runtime.h>
#include <cuda_bf16.h>
#include <cuda_fp16.h>
#include <cstdint>

#define Nn 100000
#define Ee 1600000
#define Hh 128
#define Gg 64
#define EPSf 1e-5f

#define SCAN_BS 1024
#define NBLK ((Nn + SCAN_BS - 1) / SCAN_BS)   // 98
#define BN_REP 4
#define TILES ((Nn + 255) / 256)              // 391

// ---------------- mma GEMM smem layout (256 rows per tile) ----------------
#define Pp 136                        // bf16 elements per row (272 B)
#define AIMG_B (256 * Pp * 2)         // 69632 B per A image
#define WIMG_B (128 * Pp * 2)         // 34816 B per W image
#define SM_AHI 0
#define SM_ALO AIMG_B
#define SM_W   (2 * AIMG_B)
#define SM_BN  (2 * AIMG_B + 2 * WIMG_B)
#define SM_TOTAL (SM_BN + 1024)       // 209920 B

#define MMA_BF16(d, a, b0, b1) \
    asm volatile("mma.sync.aligned.m16n8k16.row.col.f32.bf16.bf16.f32 " \
        "{%0,%1,%2,%3}, {%4,%5,%6,%7}, {%8,%9}, {%0,%1,%2,%3};" \
        : "+f"((d)[0]), "+f"((d)[1]), "+f"((d)[2]), "+f"((d)[3]) \
        : "r"((a)[0]), "r"((a)[1]), "r"((a)[2]), "r"((a)[3]), "r"(b0), "r"(b1))

// ---------------- device scratch ----------------
struct ZBlob {
    int   deg[Nn];
    int   cursor[Nn];
    float bnsum[3][BN_REP][2 * Hh];
    float xsum[Gg * Hh];
    float cnt[Gg];
};
__device__ ZBlob g_z;
__device__ float g_dinv[Nn];
__device__ int   g_off[Nn + 1];
__device__ int   g_bsum[SCAN_BS];
__device__ int2  g_csr[Ee];                       // {src, weight}
__device__ __half g_h16[(size_t)Nn * Hh];         // raw A @ W, fp16
__device__ float g_agg[(size_t)Nn * Hh];
__device__ float g_act[(size_t)Nn * Hh];
__device__ __nv_bfloat16 g_wt[3][2][128 * Pp];    // padded W^T bf16 hi/lo images

// ---------------- degree ----------------
__global__ void k_deg(const int* __restrict__ dst) {
    int e = blockIdx.x * blockDim.x + threadIdx.x;
    if (e < Ee) atomicAdd(&g_z.deg[dst[e]], 1);
}

// ---- W split: fp32 W[k][n] -> padded bf16 hi/lo images of W^T[n][k] ----
__global__ void k_wsplit(const float* __restrict__ W1, const float* __restrict__ W2,
                         const float* __restrict__ W3) {
    int layer = blockIdx.y;
    const float* Ws = (layer == 0) ? W1 : (layer == 1) ? W2 : W3;
    int n = blockIdx.x;
    int k = threadIdx.x;
    float v = Ws[k * 128 + n];
    __nv_bfloat16 hi = __float2bfloat16(v);
    float lo = v - __bfloat162float(hi);
    g_wt[layer][0][n * Pp + k] = hi;
    g_wt[layer][1][n * Pp + k] = __float2bfloat16(lo);
}

// ---------------- exclusive scan of degrees -> CSR offsets ----------------
__global__ void k_scan1() {
    __shared__ int s[SCAN_BS];
    int tid = threadIdx.x;
    int i = blockIdx.x * SCAN_BS + tid;
    int v = (i < Nn) ? g_z.deg[i] : 0;
    s[tid] = v;
    __syncthreads();
    for (int d = 1; d < SCAN_BS; d <<= 1) {
        int t = (tid >= d) ? s[tid - d] : 0;
        __syncthreads();
        s[tid] += t;
        __syncthreads();
    }
    if (i < Nn) g_off[i] = s[tid] - v;
    if (tid == SCAN_BS - 1) g_bsum[blockIdx.x] = s[tid];
}

__global__ void k_scan2() {
    __shared__ int s[128];
    int tid = threadIdx.x;
    int v = (tid < NBLK) ? g_bsum[tid] : 0;
    s[tid] = v;
    __syncthreads();
    for (int d = 1; d < 128; d <<= 1) {
        int t = (tid >= d) ? s[tid - d] : 0;
        __syncthreads();
        s[tid] += t;
        __syncthreads();
    }
    g_bsum[tid] = s[tid] - v;
}

__global__ void k_scan3() {   // + dinv
    int i = blockIdx.x * blockDim.x + threadIdx.x;
    if (i < Nn) {
        g_off[i] += g_bsum[i >> 10];
        g_dinv[i] = rsqrtf((float)g_z.deg[i] + 1.0f);
    }
    if (i == 0) g_off[Nn] = Ee;
}

__global__ void k_fill(const int* __restrict__ src, const int* __restrict__ dst) {
    int e = blockIdx.x * blockDim.x + threadIdx.x;
    if (e >= Ee) return;
    int d = dst[e];
    int s = src[e];
    int pos = g_off[d] + atomicAdd(&g_z.cursor[d], 1);
    g_csr[pos] = make_int2(s, __float_as_int(g_dinv[s] * g_dinv[d]));
}

// ---- tensor GEMM: g_h16[M,128] = fp16( A @ W ), LDS.32 frags (R8 loop) ----
// mode 0: A = Ain; mode 1: A = relu(bn(g_agg)) -> also g_act;
// mode 2: A = relu(bn(g_agg)) + g_act -> also g_act
__global__ __launch_bounds__(512)
void gemm_tc(const float* __restrict__ Ain, int layer, int mode, int bnidx,
             const float* __restrict__ gam, const float* __restrict__ bet) {
    extern __shared__ char sm[];
    float* s_bn = (float*)(sm + SM_BN);
    int tid = threadIdx.x;
    int wid = tid >> 5;
    int lane = tid & 31;
    int gid = lane >> 2;
    int tig = lane & 3;
    int row0 = blockIdx.x * 256;

    // W hi+lo images -> smem
    {
        const uint4* wsrc = (const uint4*)(&g_wt[layer][0][0]);
        uint4* wdst = (uint4*)(sm + SM_W);
        for (int i = tid; i < 4352; i += 512) wdst[i] = wsrc[i];
    }
    // BN scale/shift
    if (mode && tid < 128) {
        float s = 0.f, q = 0.f;
#pragma unroll
        for (int r = 0; r < BN_REP; r++) {
            s += g_z.bnsum[bnidx][r][tid];
            q += g_z.bnsum[bnidx][r][128 + tid];
        }
        float mean = s * (1.0f / (float)Nn);
        float var = q * (1.0f / (float)Nn) - mean * mean;
        float sc = gam[tid] * rsqrtf(var + EPSf);
        s_bn[tid] = sc;
        s_bn[128 + tid] = bet[tid] - mean * sc;
    }
    __syncthreads();

    // A prologue
    {
        int r = tid & 255;
        int half = tid >> 8;
        int gr = row0 + r;
#pragma unroll
        for (int j = 0; j < 8; j++) {
            int k0 = half * 64 + j * 8;
            float4 va = make_float4(0.f, 0.f, 0.f, 0.f), vb = va;
            if (gr < Nn) {
                if (mode == 0) {
                    const float4* ap = (const float4*)(Ain + (size_t)gr * 128 + k0);
                    va = ap[0]; vb = ap[1];
                } else {
                    const float4* ap = (const float4*)(g_agg + (size_t)gr * 128 + k0);
                    float4 a0 = ap[0], a1 = ap[1];
                    const float4* scp = (const float4*)(s_bn + k0);
                    const float4* shp = (const float4*)(s_bn + 128 + k0);
                    float4 s0 = scp[0], s1 = scp[1], h0 = shp[0], h1 = shp[1];
                    va.x = fmaxf(fmaf(a0.x, s0.x, h0.x), 0.f);
                    va.y = fmaxf(fmaf(a0.y, s0.y, h0.y), 0.f);
                    va.z = fmaxf(fmaf(a0.z, s0.z, h0.z), 0.f);
                    va.w = fmaxf(fmaf(a0.w, s0.w, h0.w), 0.f);
                    vb.x = fmaxf(fmaf(a1.x, s1.x, h1.x), 0.f);
                    vb.y = fmaxf(fmaf(a1.y, s1.y, h1.y), 0.f);
                    vb.z = fmaxf(fmaf(a1.z, s1.z, h1.z), 0.f);
                    vb.w = fmaxf(fmaf(a1.w, s1.w, h1.w), 0.f);
                    if (mode == 2) {
                        const float4* rp = (const float4*)(g_act + (size_t)gr * 128 + k0);
                        float4 r0 = rp[0], r1 = rp[1];
                        va.x += r0.x; va.y += r0.y; va.z += r0.z; va.w += r0.w;
                        vb.x += r1.x; vb.y += r1.y; vb.z += r1.z; vb.w += r1.w;
                    }
                    float4* op = (float4*)(g_act + (size_t)gr * 128 + k0);
                    op[0] = va; op[1] = vb;
                }
            }
            float vv[8] = {va.x, va.y, va.z, va.w, vb.x, vb.y, vb.z, vb.w};
            uint32_t hw[4], lw[4];
#pragma unroll
            for (int q = 0; q < 4; q++) {
                __nv_bfloat162 hb = __floats2bfloat162_rn(vv[2 * q], vv[2 * q + 1]);
                float ra = __bfloat162float(hb.x), rb = __bfloat162float(hb.y);
                __nv_bfloat162 lb = __floats2bfloat162_rn(vv[2 * q] - ra, vv[2 * q + 1] - rb);
                hw[q] = *(uint32_t*)&hb;
                lw[q] = *(uint32_t*)&lb;
            }
            size_t off = ((size_t)r * Pp + k0) * 2;
            *(uint4*)(sm + SM_AHI + off) = make_uint4(hw[0], hw[1], hw[2], hw[3]);
            *(uint4*)(sm + SM_ALO + off) = make_uint4(lw[0], lw[1], lw[2], lw[3]);
        }
    }
    __syncthreads();

    // main loop (R8: LDS.32 fragment loads), warp tile 32 rows x 64 cols
    int m0 = (wid >> 1) * 32;
    int nb = (wid & 1) * 64;

    float acc[2][8][4];
#pragma unroll
    for (int t = 0; t < 2; t++)
#pragma unroll
        for (int nt = 0; nt < 8; nt++) {
            acc[t][nt][0] = 0.f; acc[t][nt][1] = 0.f;
            acc[t][nt][2] = 0.f; acc[t][nt][3] = 0.f;
        }

#pragma unroll 1
    for (int kc = 0; kc < 8; kc++) {
        int k0 = kc * 16;
        uint32_t ah[2][4], al[2][4];
#pragma unroll
        for (int t = 0; t < 2; t++) {
            size_t o0 = ((size_t)(m0 + t * 16 + gid) * Pp + k0 + tig * 2) * 2;
            size_t o1 = ((size_t)(m0 + t * 16 + 8 + gid) * Pp + k0 + tig * 2) * 2;
            ah[t][0] = *(const uint32_t*)(sm + SM_AHI + o0);
            ah[t][1] = *(const uint32_t*)(sm + SM_AHI + o1);
            ah[t][2] = *(const uint32_t*)(sm + SM_AHI + o0 + 16);
            ah[t][3] = *(const uint32_t*)(sm + SM_AHI + o1 + 16);
            al[t][0] = *(const uint32_t*)(sm + SM_ALO + o0);
            al[t][1] = *(const uint32_t*)(sm + SM_ALO + o1);
            al[t][2] = *(const uint32_t*)(sm + SM_ALO + o0 + 16);
            al[t][3] = *(const uint32_t*)(sm + SM_ALO + o1 + 16);
        }
#pragma unroll
        for (int nt = 0; nt < 8; nt++) {
            size_t bo = ((size_t)(nb + nt * 8 + gid) * Pp + k0 + tig * 2) * 2;
            uint32_t bh0 = *(const uint32_t*)(sm + SM_W + bo);
            uint32_t bh1 = *(const uint32_t*)(sm + SM_W + bo + 16);
            uint32_t bl0 = *(const uint32_t*)(sm + SM_W + WIMG_B + bo);
            uint32_t bl1 = *(const uint32_t*)(sm + SM_W + WIMG_B + bo + 16);
#pragma unroll
            for (int t = 0; t < 2; t++) {
                MMA_BF16(acc[t][nt], ah[t], bh0, bh1);
                MMA_BF16(acc[t][nt], ah[t], bl0, bl1);
                MMA_BF16(acc[t][nt], al[t], bh0, bh1);
            }
        }
    }

    // epilogue: raw product -> fp16
#pragma unroll
    for (int t = 0; t < 2; t++) {
        int r1 = row0 + m0 + t * 16 + gid;
        int r2 = r1 + 8;
#pragma unroll
        for (int nt = 0; nt < 8; nt++) {
            int c2 = (wid & 1) * 32 + nt * 4 + tig;
            if (r1 < Nn) {
                __half2 p = __floats2half2_rn(acc[t][nt][0], acc[t][nt][1]);
                ((uint32_t*)g_h16)[(size_t)r1 * 64 + c2] = *(uint32_t*)&p;
            }
            if (r2 < Nn) {
                __half2 p = __floats2half2_rn(acc[t][nt][2], acc[t][nt][3]);
                ((uint32_t*)g_h16)[(size_t)r2 * 64 + c2] = *(uint32_t*)&p;
            }
        }
    }
}

// ------- gather: 256 threads = 8 nodes/block, 2-deep unroll, fp16 payload -------
__global__ __launch_bounds__(256) void k_gather(const float* __restrict__ bias, int bnidx) {
    __shared__ float ss[8 * 128];

    int tid = threadIdx.x;
    int wloc = tid >> 5;
    int lane = tid & 31;
    int wid = blockIdx.x * 8 + wloc;

    int beg = g_off[wid];
    int end = g_off[wid + 1];
    float di = g_dinv[wid];
    float d2 = di * di;

    const uint2* hv = (const uint2*)g_h16;
    uint2 hs = hv[(size_t)wid * 32 + lane];
    float2 f0 = __half22float2(*(__half2*)&hs.x);
    float2 f1 = __half22float2(*(__half2*)&hs.y);
    float4 acc = make_float4(f0.x * d2, f0.y * d2, f1.x * d2, f1.y * d2);
    float4 acc2 = make_float4(0.f, 0.f, 0.f, 0.f);

    const int2* csr = g_csr;
    int e = beg;
    for (; e + 2 <= end; e += 2) {
        int2 c0 = csr[e];
        int2 c1 = csr[e + 1];
        uint2 v0 = hv[(size_t)c0.x * 32 + lane];
        uint2 v1 = hv[(size_t)c1.x * 32 + lane];
        float w0 = __int_as_float(c0.y);
        float w1 = __int_as_float(c1.y);
        float2 a0 = __half22float2(*(__half2*)&v0.x);
        float2 a1 = __half22float2(*(__half2*)&v0.y);
        float2 b0 = __half22float2(*(__half2*)&v1.x);
        float2 b1 = __half22float2(*(__half2*)&v1.y);
        acc.x = fmaf(a0.x, w0, acc.x);
        acc.y = fmaf(a0.y, w0, acc.y);
        acc.z = fmaf(a1.x, w0, acc.z);
        acc.w = fmaf(a1.y, w0, acc.w);
        acc2.x = fmaf(b0.x, w1, acc2.x);
        acc2.y = fmaf(b0.y, w1, acc2.y);
        acc2.z = fmaf(b1.x, w1, acc2.z);
        acc2.w = fmaf(b1.y, w1, acc2.w);
    }
    if (e < end) {
        int2 c0 = csr[e];
        uint2 v0 = hv[(size_t)c0.x * 32 + lane];
        float w0 = __int_as_float(c0.y);
        float2 a0 = __half22float2(*(__half2*)&v0.x);
        float2 a1 = __half22float2(*(__half2*)&v0.y);
        acc.x = fmaf(a0.x, w0, acc.x);
        acc.y = fmaf(a0.y, w0, acc.y);
        acc.z = fmaf(a1.x, w0, acc.z);
        acc.w = fmaf(a1.y, w0, acc.w);
    }
    acc.x += acc2.x; acc.y += acc2.y; acc.z += acc2.z; acc.w += acc2.w;

    float4 b4 = ((const float4*)bias)[lane];
    acc.x += b4.x; acc.y += b4.y; acc.z += b4.z; acc.w += b4.w;
    ((float4*)g_agg)[(size_t)wid * 32 + lane] = acc;

    int base = wloc * 128 + lane * 4;
    ss[base + 0] = acc.x; ss[base + 1] = acc.y; ss[base + 2] = acc.z; ss[base + 3] = acc.w;
    __syncthreads();

    // 256 threads: part 0 = sum, part 1 = sumsq over 8 warps
    {
        int c = tid & 127;
        int part = tid >> 7;
        float r = 0.f;
        if (part == 0) {
#pragma unroll
            for (int w = 0; w < 8; w++) r += ss[w * 128 + c];
        } else {
#pragma unroll
            for (int w = 0; w < 8; w++) { float v = ss[w * 128 + c]; r = fmaf(v, v, r); }
        }
        atomicAdd(&g_z.bnsum[bnidx][blockIdx.x & (BN_REP - 1)][part * 128 + c], r);
    }
}

// ---------------- pooling with fused layer-3 BN finalize+apply ----------------
#define PCHUNK 256
__global__ void k_pool(const int* __restrict__ batch,
                       const float* __restrict__ gam, const float* __restrict__ bet) {
    int c = threadIdx.x;
    float s = 0.f, q = 0.f;
#pragma unroll
    for (int r = 0; r < BN_REP; r++) {
        s += g_z.bnsum[2][r][c];
        q += g_z.bnsum[2][r][128 + c];
    }
    float mean = s * (1.0f / (float)Nn);
    float var = q * (1.0f / (float)Nn) - mean * mean;
    float sc = gam[c] * rsqrtf(var + EPSf);
    float sh = bet[c] - mean * sc;

    int start = blockIdx.x * PCHUNK;
    if (start >= Nn) return;
    int end = min(start + PCHUNK, Nn);
    float acc = 0.f, ccnt = 0.f;
    int gp = batch[start];
    for (int n = start; n < end; n++) {
        int g = batch[n];
        if (g != gp) {
            atomicAdd(&g_z.xsum[gp * 128 + c], acc);
            if (c == 0) atomicAdd(&g_z.cnt[gp], ccnt);
            acc = 0.f; ccnt = 0.f; gp = g;
        }
        float a = g_agg[(size_t)n * 128 + c];
        float v = fmaxf(fmaf(a, sc, sh), 0.f) + g_act[(size_t)n * 128 + c];
        acc += v;
        ccnt += 1.f;
    }
    atomicAdd(&g_z.xsum[gp * 128 + c], acc);
    if (c == 0) atomicAdd(&g_z.cnt[gp], ccnt);
}

// ---------------- MLP head ----------------
__global__ void k_mlp(const float* __restrict__ Wm1, const float* __restrict__ bm1,
                      const float* __restrict__ Wm2, const float* __restrict__ bm2,
                      float* __restrict__ out) {
    __shared__ float zs[128], zm[128], hid[128];
    int g = blockIdx.x, c = threadIdx.x;
    float cnt = fmaxf(g_z.cnt[g], 1.0f);
    float xs = g_z.xsum[g * 128 + c];
    zs[c] = xs;
    zm[c] = xs / cnt;
    __syncthreads();
    float acc = bm1[c];
#pragma unroll 8
    for (int k = 0; k < 128; k++)
        acc += zs[k] * Wm1[k * 128 + c] + zm[k] * Wm1[(128 + k) * 128 + c];
    hid[c] = fmaxf(acc, 0.f) * Wm2[c];
    __syncthreads();
    for (int s = 64; s > 0; s >>= 1) {
        if (c < s) hid[c] += hid[c + s];
        __syncthreads();
    }
    if (c == 0) out[g] = hid[0] + bm2[0];
}

// ---------------- host ----------------
extern "C" void kernel_launch(void* const* d_in, const int* in_sizes, int n_in,
                              void* d_out, int out_size) {
    const float *x, *W1, *b1, *W2, *b2, *W3, *b3;
    const float *g1, *be1, *g2, *be2, *g3, *be3;
    const float *Wm1, *bm1, *Wm2, *bm2;
    const int *ei, *batch;

    if (in_sizes[1] == 2 * Ee) {
        x   = (const float*)d_in[0];
        ei  = (const int*)  d_in[1];
        batch = (const int*)d_in[2];
        W1 = (const float*)d_in[3];  b1 = (const float*)d_in[4];
        W2 = (const float*)d_in[5];  b2 = (const float*)d_in[6];
        W3 = (const float*)d_in[7];  b3 = (const float*)d_in[8];
        g1 = (const float*)d_in[9];  be1 = (const float*)d_in[10];
        g2 = (const float*)d_in[11]; be2 = (const float*)d_in[12];
        g3 = (const float*)d_in[13]; be3 = (const float*)d_in[14];
        Wm1 = (const float*)d_in[15]; bm1 = (const float*)d_in[16];
        Wm2 = (const float*)d_in[17]; bm2 = (const float*)d_in[18];
    } else {
        x   = (const float*)d_in[0];
        W1 = (const float*)d_in[1];  b1 = (const float*)d_in[2];
        g1 = (const float*)d_in[3];  be1 = (const float*)d_in[4];
        W2 = (const float*)d_in[5];  b2 = (const float*)d_in[6];
        g2 = (const float*)d_in[7];  be2 = (const float*)d_in[8];
        W3 = (const float*)d_in[9];  b3 = (const float*)d_in[10];
        g3 = (const float*)d_in[11]; be3 = (const float*)d_in[12];
        Wm1 = (const float*)d_in[13]; bm1 = (const float*)d_in[14];
        Wm2 = (const float*)d_in[15]; bm2 = (const float*)d_in[16];
        ei  = (const int*)d_in[17];
        batch = (const int*)d_in[18];
    }

    const int* src = ei;
    const int* dst = ei + Ee;
    float* out = (float*)d_out;

    static cudaStream_t s_side = nullptr;
    static cudaEvent_t s_e1 = nullptr, s_e2 = nullptr;
    if (!s_side) {
        cudaStreamCreateWithFlags(&s_side, cudaStreamNonBlocking);
        cudaEventCreateWithFlags(&s_e1, cudaEventDisableTiming);
        cudaEventCreateWithFlags(&s_e2, cudaEventDisableTiming);
    }

    cudaFuncSetAttribute(gemm_tc, cudaFuncAttributeMaxDynamicSharedMemorySize, SM_TOTAL);

    const int ZB = (Nn + 255) / 256;          // 391
    const int EB = (Ee + 255) / 256;          // 6250
    const int GATB = Nn / 8;                  // 12500 x 256
    const int POOLB = (Nn + PCHUNK - 1) / PCHUNK;

    // zero scratch, fork CSR build onto side stream
    void* zptr = nullptr;
    cudaGetSymbolAddress(&zptr, g_z);
    cudaMemsetAsync(zptr, 0, sizeof(ZBlob), 0);
    cudaEventRecord(s_e1, 0);
    cudaStreamWaitEvent(s_side, s_e1, 0);

    // interleaved submission: gemm1 is the 4th kernel (profiling slot)
    k_deg<<<EB, 256, 0, s_side>>>(dst);                 // 1
    k_wsplit<<<dim3(128, 3), 128>>>(W1, W2, W3);        // 2 (main)
    k_scan1<<<NBLK, SCAN_BS, 0, s_side>>>();            // 3
    gemm_tc<<<TILES, 512, SM_TOTAL>>>(x, 0, 0, 0, nullptr, nullptr);   // 4 (main)
    k_scan2<<<1, 128, 0, s_side>>>();
    k_scan3<<<ZB, 256, 0, s_side>>>();
    k_fill<<<EB, 256, 0, s_side>>>(src, dst);
    cudaEventRecord(s_e2, s_side);
    cudaStreamWaitEvent(0, s_e2, 0);

    // layer 1 aggregate + BN stats
    k_gather<<<GATB, 256>>>(b1, 0);

    // layer 2
    gemm_tc<<<TILES, 512, SM_TOTAL>>>(nullptr, 1, 1, 0, g1, be1);
    k_gather<<<GATB, 256>>>(b2, 1);

    // layer 3
    gemm_tc<<<TILES, 512, SM_TOTAL>>>(nullptr, 2, 2, 1, g2, be2);
    k_gather<<<GATB, 256>>>(b3, 2);

    // pooling + MLP
    k_pool<<<POOLB, 128>>>(batch, g3, be3);
    k_mlp<<<Gg, 128>>>(Wm1, bm1, Wm2, bm2, out);
}

// round 12
// speedup vs baseline: 1.0373x; 1.0291x over previous
#include <cuda_runtime.h>
#include <cuda_bf16.h>
#include <cuda_fp16.h>
#include <cstdint>

#define Nn 100000
#define Ee 1600000
#define Hh 128
#define Gg 64
#define EPSf 1e-5f

#define SCAN_BS 1024
#define NBLK ((Nn + SCAN_BS - 1) / SCAN_BS)   // 98
#define BN_REP 4
#define TILES ((Nn + 255) / 256)              // 391
#define DINVB ((Nn + 127) / 128)              // 782

// ---------------- mma GEMM smem layout (256 rows per tile) ----------------
#define Pp 136                        // bf16 elements per row (272 B)
#define AIMG_B (256 * Pp * 2)         // 69632 B per A image
#define WIMG_B (128 * Pp * 2)         // 34816 B per W image
#define SM_AHI 0
#define SM_ALO AIMG_B
#define SM_W   (2 * AIMG_B)
#define SM_BN  (2 * AIMG_B + 2 * WIMG_B)
#define SM_TOTAL (SM_BN + 1024)       // 209920 B

#define MMA_BF16(d, a, b0, b1) \
    asm volatile("mma.sync.aligned.m16n8k16.row.col.f32.bf16.bf16.f32 " \
        "{%0,%1,%2,%3}, {%4,%5,%6,%7}, {%8,%9}, {%0,%1,%2,%3};" \
        : "+f"((d)[0]), "+f"((d)[1]), "+f"((d)[2]), "+f"((d)[3]) \
        : "r"((a)[0]), "r"((a)[1]), "r"((a)[2]), "r"((a)[3]), "r"(b0), "r"(b1))

// ---------------- device scratch ----------------
struct ZBlob {
    int   deg[Nn];
    int   cursor[Nn];
    float bnsum[3][BN_REP][2 * Hh];
    float xsum[Gg * Hh];
    float cnt[Gg];
};
__device__ ZBlob g_z;
__device__ float g_dinv[Nn];
__device__ int   g_off[Nn + 1];
__device__ int   g_bsum[SCAN_BS];
__device__ int   g_csr[Ee];                       // src only (weights folded into h')
__device__ __half g_h16[(size_t)Nn * Hh];         // h' = dinv * (A @ W), fp16
__device__ float g_agg[(size_t)Nn * Hh];
__device__ float g_act[(size_t)Nn * Hh];
__device__ __nv_bfloat16 g_wt[3][2][128 * Pp];    // padded W^T bf16 hi/lo images

// ---------------- degree ----------------
__global__ void k_deg(const int* __restrict__ dst) {
    int e = blockIdx.x * blockDim.x + threadIdx.x;
    if (e < Ee) atomicAdd(&g_z.deg[dst[e]], 1);
}

// ---- prep: dinv (blocks [0,DINVB)) + W split (blocks [DINVB, DINVB+384)) ----
__global__ void k_prep(const float* __restrict__ W1, const float* __restrict__ W2,
                       const float* __restrict__ W3) {
    int b = blockIdx.x;
    if (b < DINVB) {
        int i = b * 128 + threadIdx.x;
        if (i < Nn) g_dinv[i] = rsqrtf((float)g_z.deg[i] + 1.0f);
    } else {
        int bi = b - DINVB;                 // 0..383
        int layer = bi >> 7;
        int n = bi & 127;
        const float* Ws = (layer == 0) ? W1 : (layer == 1) ? W2 : W3;
        int k = threadIdx.x;
        float v = Ws[k * 128 + n];
        __nv_bfloat16 hi = __float2bfloat16(v);
        float lo = v - __bfloat162float(hi);
        g_wt[layer][0][n * Pp + k] = hi;
        g_wt[layer][1][n * Pp + k] = __float2bfloat16(lo);
    }
}

// ---------------- exclusive scan of degrees -> CSR offsets ----------------
__global__ void k_scan1() {
    __shared__ int s[SCAN_BS];
    int tid = threadIdx.x;
    int i = blockIdx.x * SCAN_BS + tid;
    int v = (i < Nn) ? g_z.deg[i] : 0;
    s[tid] = v;
    __syncthreads();
    for (int d = 1; d < SCAN_BS; d <<= 1) {
        int t = (tid >= d) ? s[tid - d] : 0;
        __syncthreads();
        s[tid] += t;
        __syncthreads();
    }
    if (i < Nn) g_off[i] = s[tid] - v;
    if (tid == SCAN_BS - 1) g_bsum[blockIdx.x] = s[tid];
}

__global__ void k_scan2() {
    __shared__ int s[128];
    int tid = threadIdx.x;
    int v = (tid < NBLK) ? g_bsum[tid] : 0;
    s[tid] = v;
    __syncthreads();
    for (int d = 1; d < 128; d <<= 1) {
        int t = (tid >= d) ? s[tid - d] : 0;
        __syncthreads();
        s[tid] += t;
        __syncthreads();
    }
    g_bsum[tid] = s[tid] - v;
}

__global__ void k_scan3() {
    int i = blockIdx.x * blockDim.x + threadIdx.x;
    if (i < Nn) g_off[i] += g_bsum[i >> 10];
    if (i == 0) g_off[Nn] = Ee;
}

__global__ void k_fill(const int* __restrict__ src, const int* __restrict__ dst) {
    int e = blockIdx.x * blockDim.x + threadIdx.x;
    if (e >= Ee) return;
    int d = dst[e];
    int pos = g_off[d] + atomicAdd(&g_z.cursor[d], 1);
    g_csr[pos] = src[e];
}

// ---- tensor GEMM: g_h16[M,128] = fp16( dinv * (A @ W) ), LDS.32 frags ----
// mode 0: A = Ain; mode 1: A = relu(bn(g_agg)) -> also g_act;
// mode 2: A = relu(bn(g_agg)) + g_act -> also g_act
__global__ __launch_bounds__(512)
void gemm_tc(const float* __restrict__ Ain, int layer, int mode, int bnidx,
             const float* __restrict__ gam, const float* __restrict__ bet) {
    extern __shared__ char sm[];
    float* s_bn = (float*)(sm + SM_BN);
    int tid = threadIdx.x;
    int wid = tid >> 5;
    int lane = tid & 31;
    int gid = lane >> 2;
    int tig = lane & 3;
    int row0 = blockIdx.x * 256;

    // W hi+lo images -> smem
    {
        const uint4* wsrc = (const uint4*)(&g_wt[layer][0][0]);
        uint4* wdst = (uint4*)(sm + SM_W);
        for (int i = tid; i < 4352; i += 512) wdst[i] = wsrc[i];
    }
    // BN scale/shift
    if (mode && tid < 128) {
        float s = 0.f, q = 0.f;
#pragma unroll
        for (int r = 0; r < BN_REP; r++) {
            s += g_z.bnsum[bnidx][r][tid];
            q += g_z.bnsum[bnidx][r][128 + tid];
        }
        float mean = s * (1.0f / (float)Nn);
        float var = q * (1.0f / (float)Nn) - mean * mean;
        float sc = gam[tid] * rsqrtf(var + EPSf);
        s_bn[tid] = sc;
        s_bn[128 + tid] = bet[tid] - mean * sc;
    }
    __syncthreads();

    // A prologue
    {
        int r = tid & 255;
        int half = tid >> 8;
        int gr = row0 + r;
#pragma unroll
        for (int j = 0; j < 8; j++) {
            int k0 = half * 64 + j * 8;
            float4 va = make_float4(0.f, 0.f, 0.f, 0.f), vb = va;
            if (gr < Nn) {
                if (mode == 0) {
                    const float4* ap = (const float4*)(Ain + (size_t)gr * 128 + k0);
                    va = ap[0]; vb = ap[1];
                } else {
                    const float4* ap = (const float4*)(g_agg + (size_t)gr * 128 + k0);
                    float4 a0 = ap[0], a1 = ap[1];
                    const float4* scp = (const float4*)(s_bn + k0);
                    const float4* shp = (const float4*)(s_bn + 128 + k0);
                    float4 s0 = scp[0], s1 = scp[1], h0 = shp[0], h1 = shp[1];
                    va.x = fmaxf(fmaf(a0.x, s0.x, h0.x), 0.f);
                    va.y = fmaxf(fmaf(a0.y, s0.y, h0.y), 0.f);
                    va.z = fmaxf(fmaf(a0.z, s0.z, h0.z), 0.f);
                    va.w = fmaxf(fmaf(a0.w, s0.w, h0.w), 0.f);
                    vb.x = fmaxf(fmaf(a1.x, s1.x, h1.x), 0.f);
                    vb.y = fmaxf(fmaf(a1.y, s1.y, h1.y), 0.f);
                    vb.z = fmaxf(fmaf(a1.z, s1.z, h1.z), 0.f);
                    vb.w = fmaxf(fmaf(a1.w, s1.w, h1.w), 0.f);
                    if (mode == 2) {
                        const float4* rp = (const float4*)(g_act + (size_t)gr * 128 + k0);
                        float4 r0 = rp[0], r1 = rp[1];
                        va.x += r0.x; va.y += r0.y; va.z += r0.z; va.w += r0.w;
                        vb.x += r1.x; vb.y += r1.y; vb.z += r1.z; vb.w += r1.w;
                    }
                    float4* op = (float4*)(g_act + (size_t)gr * 128 + k0);
                    op[0] = va; op[1] = vb;
                }
            }
            float vv[8] = {va.x, va.y, va.z, va.w, vb.x, vb.y, vb.z, vb.w};
            uint32_t hw[4], lw[4];
#pragma unroll
            for (int q = 0; q < 4; q++) {
                __nv_bfloat162 hb = __floats2bfloat162_rn(vv[2 * q], vv[2 * q + 1]);
                float ra = __bfloat162float(hb.x), rb = __bfloat162float(hb.y);
                __nv_bfloat162 lb = __floats2bfloat162_rn(vv[2 * q] - ra, vv[2 * q + 1] - rb);
                hw[q] = *(uint32_t*)&hb;
                lw[q] = *(uint32_t*)&lb;
            }
            size_t off = ((size_t)r * Pp + k0) * 2;
            *(uint4*)(sm + SM_AHI + off) = make_uint4(hw[0], hw[1], hw[2], hw[3]);
            *(uint4*)(sm + SM_ALO + off) = make_uint4(lw[0], lw[1], lw[2], lw[3]);
        }
    }
    __syncthreads();

    // main loop (LDS.32 fragment loads), warp tile 32 rows x 64 cols
    int m0 = (wid >> 1) * 32;
    int nb = (wid & 1) * 64;

    float acc[2][8][4];
#pragma unroll
    for (int t = 0; t < 2; t++)
#pragma unroll
        for (int nt = 0; nt < 8; nt++) {
            acc[t][nt][0] = 0.f; acc[t][nt][1] = 0.f;
            acc[t][nt][2] = 0.f; acc[t][nt][3] = 0.f;
        }

#pragma unroll 1
    for (int kc = 0; kc < 8; kc++) {
        int k0 = kc * 16;
        uint32_t ah[2][4], al[2][4];
#pragma unroll
        for (int t = 0; t < 2; t++) {
            size_t o0 = ((size_t)(m0 + t * 16 + gid) * Pp + k0 + tig * 2) * 2;
            size_t o1 = ((size_t)(m0 + t * 16 + 8 + gid) * Pp + k0 + tig * 2) * 2;
            ah[t][0] = *(const uint32_t*)(sm + SM_AHI + o0);
            ah[t][1] = *(const uint32_t*)(sm + SM_AHI + o1);
            ah[t][2] = *(const uint32_t*)(sm + SM_AHI + o0 + 16);
            ah[t][3] = *(const uint32_t*)(sm + SM_AHI + o1 + 16);
            al[t][0] = *(const uint32_t*)(sm + SM_ALO + o0);
            al[t][1] = *(const uint32_t*)(sm + SM_ALO + o1);
            al[t][2] = *(const uint32_t*)(sm + SM_ALO + o0 + 16);
            al[t][3] = *(const uint32_t*)(sm + SM_ALO + o1 + 16);
        }
#pragma unroll
        for (int nt = 0; nt < 8; nt++) {
            size_t bo = ((size_t)(nb + nt * 8 + gid) * Pp + k0 + tig * 2) * 2;
            uint32_t bh0 = *(const uint32_t*)(sm + SM_W + bo);
            uint32_t bh1 = *(const uint32_t*)(sm + SM_W + bo + 16);
            uint32_t bl0 = *(const uint32_t*)(sm + SM_W + WIMG_B + bo);
            uint32_t bl1 = *(const uint32_t*)(sm + SM_W + WIMG_B + bo + 16);
#pragma unroll
            for (int t = 0; t < 2; t++) {
                MMA_BF16(acc[t][nt], ah[t], bh0, bh1);
                MMA_BF16(acc[t][nt], ah[t], bl0, bl1);
                MMA_BF16(acc[t][nt], al[t], bh0, bh1);
            }
        }
    }

    // epilogue: scale by dinv, convert to fp16
#pragma unroll
    for (int t = 0; t < 2; t++) {
        int r1 = row0 + m0 + t * 16 + gid;
        int r2 = r1 + 8;
        float dv1 = (r1 < Nn) ? g_dinv[r1] : 0.f;
        float dv2 = (r2 < Nn) ? g_dinv[r2] : 0.f;
#pragma unroll
        for (int nt = 0; nt < 8; nt++) {
            int c2 = (wid & 1) * 32 + nt * 4 + tig;
            if (r1 < Nn) {
                __half2 p = __floats2half2_rn(acc[t][nt][0] * dv1, acc[t][nt][1] * dv1);
                ((uint32_t*)g_h16)[(size_t)r1 * 64 + c2] = *(uint32_t*)&p;
            }
            if (r2 < Nn) {
                __half2 p = __floats2half2_rn(acc[t][nt][2] * dv2, acc[t][nt][3] * dv2);
                ((uint32_t*)g_h16)[(size_t)r2 * 64 + c2] = *(uint32_t*)&p;
            }
        }
    }
}

// ------- gather (R8 form): 512 threads = 16 nodes, src-only CSR -------
// agg[d] = dinv[d] * (h'[d] + sum_e h'[src_e]) + bias
__global__ __launch_bounds__(512) void k_gather(const float* __restrict__ bias, int bnidx) {
    __shared__ float ss[16 * 128];

    int tid = threadIdx.x;
    int wloc = tid >> 5;
    int lane = tid & 31;
    int wid = blockIdx.x * 16 + wloc;

    int beg = g_off[wid];
    int end = g_off[wid + 1];
    float dn = g_dinv[wid];

    const uint2* hv = (const uint2*)g_h16;
    uint2 hs = hv[(size_t)wid * 32 + lane];
    float2 f0 = __half22float2(*(__half2*)&hs.x);
    float2 f1 = __half22float2(*(__half2*)&hs.y);
    float4 acc = make_float4(f0.x, f0.y, f1.x, f1.y);
    float4 acc2 = make_float4(0.f, 0.f, 0.f, 0.f);

    const int* csr = g_csr;
    int e = beg;
    for (; e + 2 <= end; e += 2) {
        int s0 = csr[e];
        int s1 = csr[e + 1];
        uint2 v0 = hv[(size_t)s0 * 32 + lane];
        uint2 v1 = hv[(size_t)s1 * 32 + lane];
        float2 a0 = __half22float2(*(__half2*)&v0.x);
        float2 a1 = __half22float2(*(__half2*)&v0.y);
        float2 b0 = __half22float2(*(__half2*)&v1.x);
        float2 b1 = __half22float2(*(__half2*)&v1.y);
        acc.x += a0.x; acc.y += a0.y; acc.z += a1.x; acc.w += a1.y;
        acc2.x += b0.x; acc2.y += b0.y; acc2.z += b1.x; acc2.w += b1.y;
    }
    if (e < end) {
        int s0 = csr[e];
        uint2 v0 = hv[(size_t)s0 * 32 + lane];
        float2 a0 = __half22float2(*(__half2*)&v0.x);
        float2 a1 = __half22float2(*(__half2*)&v0.y);
        acc.x += a0.x; acc.y += a0.y; acc.z += a1.x; acc.w += a1.y;
    }
    acc.x += acc2.x; acc.y += acc2.y; acc.z += acc2.z; acc.w += acc2.w;

    float4 b4 = ((const float4*)bias)[lane];
    acc.x = fmaf(acc.x, dn, b4.x);
    acc.y = fmaf(acc.y, dn, b4.y);
    acc.z = fmaf(acc.z, dn, b4.z);
    acc.w = fmaf(acc.w, dn, b4.w);
    ((float4*)g_agg)[(size_t)wid * 32 + lane] = acc;

    int base = wloc * 128 + lane * 4;
    ss[base + 0] = acc.x; ss[base + 1] = acc.y; ss[base + 2] = acc.z; ss[base + 3] = acc.w;
    __syncthreads();

    if (tid < 256) {
        int c = tid & 127;
        int part = tid >> 7;
        float r = 0.f;
        if (part == 0) {
#pragma unroll
            for (int w = 0; w < 16; w++) r += ss[w * 128 + c];
        } else {
#pragma unroll
            for (int w = 0; w < 16; w++) { float v = ss[w * 128 + c]; r = fmaf(v, v, r); }
        }
        atomicAdd(&g_z.bnsum[bnidx][blockIdx.x & (BN_REP - 1)][part * 128 + c], r);
    }
}

// ---------------- pooling with fused layer-3 BN finalize+apply ----------------
#define PCHUNK 256
__global__ void k_pool(const int* __restrict__ batch,
                       const float* __restrict__ gam, const float* __restrict__ bet) {
    int c = threadIdx.x;
    float s = 0.f, q = 0.f;
#pragma unroll
    for (int r = 0; r < BN_REP; r++) {
        s += g_z.bnsum[2][r][c];
        q += g_z.bnsum[2][r][128 + c];
    }
    float mean = s * (1.0f / (float)Nn);
    float var = q * (1.0f / (float)Nn) - mean * mean;
    float sc = gam[c] * rsqrtf(var + EPSf);
    float sh = bet[c] - mean * sc;

    int start = blockIdx.x * PCHUNK;
    if (start >= Nn) return;
    int end = min(start + PCHUNK, Nn);
    float acc = 0.f, ccnt = 0.f;
    int gp = batch[start];
    for (int n = start; n < end; n++) {
        int g = batch[n];
        if (g != gp) {
            atomicAdd(&g_z.xsum[gp * 128 + c], acc);
            if (c == 0) atomicAdd(&g_z.cnt[gp], ccnt);
            acc = 0.f; ccnt = 0.f; gp = g;
        }
        float a = g_agg[(size_t)n * 128 + c];
        float v = fmaxf(fmaf(a, sc, sh), 0.f) + g_act[(size_t)n * 128 + c];
        acc += v;
        ccnt += 1.f;
    }
    atomicAdd(&g_z.xsum[gp * 128 + c], acc);
    if (c == 0) atomicAdd(&g_z.cnt[gp], ccnt);
}

// ---------------- MLP head ----------------
__global__ void k_mlp(const float* __restrict__ Wm1, const float* __restrict__ bm1,
                      const float* __restrict__ Wm2, const float* __restrict__ bm2,
                      float* __restrict__ out) {
    __shared__ float zs[128], zm[128], hid[128];
    int g = blockIdx.x, c = threadIdx.x;
    float cnt = fmaxf(g_z.cnt[g], 1.0f);
    float xs = g_z.xsum[g * 128 + c];
    zs[c] = xs;
    zm[c] = xs / cnt;
    __syncthreads();
    float acc = bm1[c];
#pragma unroll 8
    for (int k = 0; k < 128; k++)
        acc += zs[k] * Wm1[k * 128 + c] + zm[k] * Wm1[(128 + k) * 128 + c];
    hid[c] = fmaxf(acc, 0.f) * Wm2[c];
    __syncthreads();
    for (int s = 64; s > 0; s >>= 1) {
        if (c < s) hid[c] += hid[c + s];
        __syncthreads();
    }
    if (c == 0) out[g] = hid[0] + bm2[0];
}

// ---------------- host ----------------
extern "C" void kernel_launch(void* const* d_in, const int* in_sizes, int n_in,
                              void* d_out, int out_size) {
    const float *x, *W1, *b1, *W2, *b2, *W3, *b3;
    const float *g1, *be1, *g2, *be2, *g3, *be3;
    const float *Wm1, *bm1, *Wm2, *bm2;
    const int *ei, *batch;

    if (in_sizes[1] == 2 * Ee) {
        x   = (const float*)d_in[0];
        ei  = (const int*)  d_in[1];
        batch = (const int*)d_in[2];
        W1 = (const float*)d_in[3];  b1 = (const float*)d_in[4];
        W2 = (const float*)d_in[5];  b2 = (const float*)d_in[6];
        W3 = (const float*)d_in[7];  b3 = (const float*)d_in[8];
        g1 = (const float*)d_in[9];  be1 = (const float*)d_in[10];
        g2 = (const float*)d_in[11]; be2 = (const float*)d_in[12];
        g3 = (const float*)d_in[13]; be3 = (const float*)d_in[14];
        Wm1 = (const float*)d_in[15]; bm1 = (const float*)d_in[16];
        Wm2 = (const float*)d_in[17]; bm2 = (const float*)d_in[18];
    } else {
        x   = (const float*)d_in[0];
        W1 = (const float*)d_in[1];  b1 = (const float*)d_in[2];
        g1 = (const float*)d_in[3];  be1 = (const float*)d_in[4];
        W2 = (const float*)d_in[5];  b2 = (const float*)d_in[6];
        g2 = (const float*)d_in[7];  be2 = (const float*)d_in[8];
        W3 = (const float*)d_in[9];  b3 = (const float*)d_in[10];
        g3 = (const float*)d_in[11]; be3 = (const float*)d_in[12];
        Wm1 = (const float*)d_in[13]; bm1 = (const float*)d_in[14];
        Wm2 = (const float*)d_in[15]; bm2 = (const float*)d_in[16];
        ei  = (const int*)d_in[17];
        batch = (const int*)d_in[18];
    }

    const int* src = ei;
    const int* dst = ei + Ee;
    float* out = (float*)d_out;

    static cudaStream_t s_side = nullptr;
    static cudaEvent_t s_e1 = nullptr, s_e2 = nullptr;
    if (!s_side) {
        cudaStreamCreateWithFlags(&s_side, cudaStreamNonBlocking);
        cudaEventCreateWithFlags(&s_e1, cudaEventDisableTiming);
        cudaEventCreateWithFlags(&s_e2, cudaEventDisableTiming);
    }

    cudaFuncSetAttribute(gemm_tc, cudaFuncAttributeMaxDynamicSharedMemorySize, SM_TOTAL);

    const int ZB = (Nn + 255) / 256;          // 391
    const int EB = (Ee + 255) / 256;          // 6250
    const int GATB = (Nn + 15) / 16;          // 6250 x 512
    const int POOLB = (Nn + PCHUNK - 1) / PCHUNK;

    // zero scratch with one memset
    void* zptr = nullptr;
    cudaGetSymbolAddress(&zptr, g_z);
    cudaMemsetAsync(zptr, 0, sizeof(ZBlob), 0);

    // deg on main stream (everything depends on it)
    k_deg<<<EB, 256>>>(dst);                          // kernel 1
    cudaEventRecord(s_e1, 0);
    cudaStreamWaitEvent(s_side, s_e1, 0);

    // side stream: scan1 -> scan2 -> scan3 -> fill (independent of dinv; src-only CSR)
    // main stream: prep (dinv + wsplit) -> gemm1 (profiling slot: 4th kernel)
    k_prep<<<DINVB + 384, 128>>>(W1, W2, W3);         // kernel 2 (main)
    k_scan1<<<NBLK, SCAN_BS, 0, s_side>>>();          // kernel 3 (side)
    gemm_tc<<<TILES, 512, SM_TOTAL>>>(x, 0, 0, 0, nullptr, nullptr);   // kernel 4 (main)
    k_scan2<<<1, 128, 0, s_side>>>();
    k_scan3<<<ZB, 256, 0, s_side>>>();
    k_fill<<<EB, 256, 0, s_side>>>(src, dst);
    cudaEventRecord(s_e2, s_side);
    cudaStreamWaitEvent(0, s_e2, 0);

    // layer 1 aggregate + BN stats
    k_gather<<<GATB, 512>>>(b1, 0);

    // layer 2
    gemm_tc<<<TILES, 512, SM_TOTAL>>>(nullptr, 1, 1, 0, g1, be1);
    k_gather<<<GATB, 512>>>(b2, 1);

    // layer 3
    gemm_tc<<<TILES, 512, SM_TOTAL>>>(nullptr, 2, 2, 1, g2, be2);
    k_gather<<<GATB, 512>>>(b3, 2);

    // pooling + MLP
    k_pool<<<POOLB, 128>>>(batch, g3, be3);
    k_mlp<<<Gg, 128>>>(Wm1, bm1, Wm2, bm2, out);
}

// round 13
// speedup vs baseline: 1.1560x; 1.1145x over previous
#include <cuda_runtime.h>
#include <cuda_bf16.h>
#include <cuda_fp16.h>
#include <cstdint>

#define Nn 100000
#define Ee 1600000
#define Hh 128
#define Gg 64
#define EPSf 1e-5f

#define SCAN_BS 1024
#define NBLK ((Nn + SCAN_BS - 1) / SCAN_BS)   // 98
#define BN_REP 4
#define TILES ((Nn + 255) / 256)              // 391
#define DINVB ((Nn + 127) / 128)              // 782

// ---------------- mma GEMM smem layout (256 rows per tile) ----------------
#define Pp 136                        // bf16 elements per row (272 B)
#define AIMG_B (256 * Pp * 2)         // 69632 B per A image
#define WIMG_B (128 * Pp * 2)         // 34816 B per W image
#define SM_AHI 0
#define SM_ALO AIMG_B
#define SM_W   (2 * AIMG_B)
#define SM_BN  (2 * AIMG_B + 2 * WIMG_B)
#define SM_TOTAL (SM_BN + 1024)       // 209920 B

#define MMA_BF16(d, a, b0, b1) \
    asm volatile("mma.sync.aligned.m16n8k16.row.col.f32.bf16.bf16.f32 " \
        "{%0,%1,%2,%3}, {%4,%5,%6,%7}, {%8,%9}, {%0,%1,%2,%3};" \
        : "+f"((d)[0]), "+f"((d)[1]), "+f"((d)[2]), "+f"((d)[3]) \
        : "r"((a)[0]), "r"((a)[1]), "r"((a)[2]), "r"((a)[3]), "r"(b0), "r"(b1))

// ---------------- device scratch ----------------
struct ZBlob {
    int   deg[Nn];
    int   cursor[Nn];
    float bnsum[3][BN_REP][2 * Hh];
    float xsum[Gg * Hh];
    float cnt[Gg];
};
__device__ ZBlob g_z;
__device__ float g_dinv[Nn];
__device__ int   g_off[Nn + 1];
__device__ int   g_bsum[SCAN_BS];
__device__ int   g_csr[Ee];                       // src only (weights folded into h')
__device__ __half g_h16[(size_t)Nn * Hh];         // h' = dinv * (A @ W), fp16
__device__ float g_agg[(size_t)Nn * Hh];
__device__ float g_act[(size_t)Nn * Hh];
__device__ __nv_bfloat16 g_wt[3][2][128 * Pp];    // padded W^T bf16 hi/lo images

// ---------------- degree ----------------
__global__ void k_deg(const int* __restrict__ dst) {
    int e = blockIdx.x * blockDim.x + threadIdx.x;
    if (e < Ee) atomicAdd(&g_z.deg[dst[e]], 1);
}

// ---- prep: dinv (blocks [0,DINVB)) + W split (blocks [DINVB, DINVB+384)) ----
__global__ void k_prep(const float* __restrict__ W1, const float* __restrict__ W2,
                       const float* __restrict__ W3) {
    int b = blockIdx.x;
    if (b < DINVB) {
        int i = b * 128 + threadIdx.x;
        if (i < Nn) g_dinv[i] = rsqrtf((float)g_z.deg[i] + 1.0f);
    } else {
        int bi = b - DINVB;                 // 0..383
        int layer = bi >> 7;
        int n = bi & 127;
        const float* Ws = (layer == 0) ? W1 : (layer == 1) ? W2 : W3;
        int k = threadIdx.x;
        float v = Ws[k * 128 + n];
        __nv_bfloat16 hi = __float2bfloat16(v);
        float lo = v - __bfloat162float(hi);
        g_wt[layer][0][n * Pp + k] = hi;
        g_wt[layer][1][n * Pp + k] = __float2bfloat16(lo);
    }
}

// ---------------- exclusive scan of degrees -> CSR offsets ----------------
__global__ void k_scan1() {
    __shared__ int s[SCAN_BS];
    int tid = threadIdx.x;
    int i = blockIdx.x * SCAN_BS + tid;
    int v = (i < Nn) ? g_z.deg[i] : 0;
    s[tid] = v;
    __syncthreads();
    for (int d = 1; d < SCAN_BS; d <<= 1) {
        int t = (tid >= d) ? s[tid - d] : 0;
        __syncthreads();
        s[tid] += t;
        __syncthreads();
    }
    if (i < Nn) g_off[i] = s[tid] - v;
    if (tid == SCAN_BS - 1) g_bsum[blockIdx.x] = s[tid];
}

__global__ void k_scan2() {
    __shared__ int s[128];
    int tid = threadIdx.x;
    int v = (tid < NBLK) ? g_bsum[tid] : 0;
    s[tid] = v;
    __syncthreads();
    for (int d = 1; d < 128; d <<= 1) {
        int t = (tid >= d) ? s[tid - d] : 0;
        __syncthreads();
        s[tid] += t;
        __syncthreads();
    }
    g_bsum[tid] = s[tid] - v;
}

__global__ void k_scan3() {
    int i = blockIdx.x * blockDim.x + threadIdx.x;
    if (i < Nn) g_off[i] += g_bsum[i >> 10];
    if (i == 0) g_off[Nn] = Ee;
}

__global__ void k_fill(const int* __restrict__ src, const int* __restrict__ dst) {
    int e = blockIdx.x * blockDim.x + threadIdx.x;
    if (e >= Ee) return;
    int d = dst[e];
    int pos = g_off[d] + atomicAdd(&g_z.cursor[d], 1);
    g_csr[pos] = src[e];
}

// ---- tensor GEMM: g_h16[M,128] = fp16( dinv * (A @ W) ), LDS.32 frags ----
__global__ __launch_bounds__(512)
void gemm_tc(const float* __restrict__ Ain, int layer, int mode, int bnidx,
             const float* __restrict__ gam, const float* __restrict__ bet) {
    extern __shared__ char sm[];
    float* s_bn = (float*)(sm + SM_BN);
    int tid = threadIdx.x;
    int wid = tid >> 5;
    int lane = tid & 31;
    int gid = lane >> 2;
    int tig = lane & 3;
    int row0 = blockIdx.x * 256;

    {
        const uint4* wsrc = (const uint4*)(&g_wt[layer][0][0]);
        uint4* wdst = (uint4*)(sm + SM_W);
        for (int i = tid; i < 4352; i += 512) wdst[i] = wsrc[i];
    }
    if (mode && tid < 128) {
        float s = 0.f, q = 0.f;
#pragma unroll
        for (int r = 0; r < BN_REP; r++) {
            s += g_z.bnsum[bnidx][r][tid];
            q += g_z.bnsum[bnidx][r][128 + tid];
        }
        float mean = s * (1.0f / (float)Nn);
        float var = q * (1.0f / (float)Nn) - mean * mean;
        float sc = gam[tid] * rsqrtf(var + EPSf);
        s_bn[tid] = sc;
        s_bn[128 + tid] = bet[tid] - mean * sc;
    }
    __syncthreads();

    {
        int r = tid & 255;
        int half = tid >> 8;
        int gr = row0 + r;
#pragma unroll
        for (int j = 0; j < 8; j++) {
            int k0 = half * 64 + j * 8;
            float4 va = make_float4(0.f, 0.f, 0.f, 0.f), vb = va;
            if (gr < Nn) {
                if (mode == 0) {
                    const float4* ap = (const float4*)(Ain + (size_t)gr * 128 + k0);
                    va = ap[0]; vb = ap[1];
                } else {
                    const float4* ap = (const float4*)(g_agg + (size_t)gr * 128 + k0);
                    float4 a0 = ap[0], a1 = ap[1];
                    const float4* scp = (const float4*)(s_bn + k0);
                    const float4* shp = (const float4*)(s_bn + 128 + k0);
                    float4 s0 = scp[0], s1 = scp[1], h0 = shp[0], h1 = shp[1];
                    va.x = fmaxf(fmaf(a0.x, s0.x, h0.x), 0.f);
                    va.y = fmaxf(fmaf(a0.y, s0.y, h0.y), 0.f);
                    va.z = fmaxf(fmaf(a0.z, s0.z, h0.z), 0.f);
                    va.w = fmaxf(fmaf(a0.w, s0.w, h0.w), 0.f);
                    vb.x = fmaxf(fmaf(a1.x, s1.x, h1.x), 0.f);
                    vb.y = fmaxf(fmaf(a1.y, s1.y, h1.y), 0.f);
                    vb.z = fmaxf(fmaf(a1.z, s1.z, h1.z), 0.f);
                    vb.w = fmaxf(fmaf(a1.w, s1.w, h1.w), 0.f);
                    if (mode == 2) {
                        const float4* rp = (const float4*)(g_act + (size_t)gr * 128 + k0);
                        float4 r0 = rp[0], r1 = rp[1];
                        va.x += r0.x; va.y += r0.y; va.z += r0.z; va.w += r0.w;
                        vb.x += r1.x; vb.y += r1.y; vb.z += r1.z; vb.w += r1.w;
                    }
                    float4* op = (float4*)(g_act + (size_t)gr * 128 + k0);
                    op[0] = va; op[1] = vb;
                }
            }
            float vv[8] = {va.x, va.y, va.z, va.w, vb.x, vb.y, vb.z, vb.w};
            uint32_t hw[4], lw[4];
#pragma unroll
            for (int q = 0; q < 4; q++) {
                __nv_bfloat162 hb = __floats2bfloat162_rn(vv[2 * q], vv[2 * q + 1]);
                float ra = __bfloat162float(hb.x), rb = __bfloat162float(hb.y);
                __nv_bfloat162 lb = __floats2bfloat162_rn(vv[2 * q] - ra, vv[2 * q + 1] - rb);
                hw[q] = *(uint32_t*)&hb;
                lw[q] = *(uint32_t*)&lb;
            }
            size_t off = ((size_t)r * Pp + k0) * 2;
            *(uint4*)(sm + SM_AHI + off) = make_uint4(hw[0], hw[1], hw[2], hw[3]);
            *(uint4*)(sm + SM_ALO + off) = make_uint4(lw[0], lw[1], lw[2], lw[3]);
        }
    }
    __syncthreads();

    int m0 = (wid >> 1) * 32;
    int nb = (wid & 1) * 64;

    float acc[2][8][4];
#pragma unroll
    for (int t = 0; t < 2; t++)
#pragma unroll
        for (int nt = 0; nt < 8; nt++) {
            acc[t][nt][0] = 0.f; acc[t][nt][1] = 0.f;
            acc[t][nt][2] = 0.f; acc[t][nt][3] = 0.f;
        }

#pragma unroll 1
    for (int kc = 0; kc < 8; kc++) {
        int k0 = kc * 16;
        uint32_t ah[2][4], al[2][4];
#pragma unroll
        for (int t = 0; t < 2; t++) {
            size_t o0 = ((size_t)(m0 + t * 16 + gid) * Pp + k0 + tig * 2) * 2;
            size_t o1 = ((size_t)(m0 + t * 16 + 8 + gid) * Pp + k0 + tig * 2) * 2;
            ah[t][0] = *(const uint32_t*)(sm + SM_AHI + o0);
            ah[t][1] = *(const uint32_t*)(sm + SM_AHI + o1);
            ah[t][2] = *(const uint32_t*)(sm + SM_AHI + o0 + 16);
            ah[t][3] = *(const uint32_t*)(sm + SM_AHI + o1 + 16);
            al[t][0] = *(const uint32_t*)(sm + SM_ALO + o0);
            al[t][1] = *(const uint32_t*)(sm + SM_ALO + o1);
            al[t][2] = *(const uint32_t*)(sm + SM_ALO + o0 + 16);
            al[t][3] = *(const uint32_t*)(sm + SM_ALO + o1 + 16);
        }
#pragma unroll
        for (int nt = 0; nt < 8; nt++) {
            size_t bo = ((size_t)(nb + nt * 8 + gid) * Pp + k0 + tig * 2) * 2;
            uint32_t bh0 = *(const uint32_t*)(sm + SM_W + bo);
            uint32_t bh1 = *(const uint32_t*)(sm + SM_W + bo + 16);
            uint32_t bl0 = *(const uint32_t*)(sm + SM_W + WIMG_B + bo);
            uint32_t bl1 = *(const uint32_t*)(sm + SM_W + WIMG_B + bo + 16);
#pragma unroll
            for (int t = 0; t < 2; t++) {
                MMA_BF16(acc[t][nt], ah[t], bh0, bh1);
                MMA_BF16(acc[t][nt], ah[t], bl0, bl1);
                MMA_BF16(acc[t][nt], al[t], bh0, bh1);
            }
        }
    }

#pragma unroll
    for (int t = 0; t < 2; t++) {
        int r1 = row0 + m0 + t * 16 + gid;
        int r2 = r1 + 8;
        float dv1 = (r1 < Nn) ? g_dinv[r1] : 0.f;
        float dv2 = (r2 < Nn) ? g_dinv[r2] : 0.f;
#pragma unroll
        for (int nt = 0; nt < 8; nt++) {
            int c2 = (wid & 1) * 32 + nt * 4 + tig;
            if (r1 < Nn) {
                __half2 p = __floats2half2_rn(acc[t][nt][0] * dv1, acc[t][nt][1] * dv1);
                ((uint32_t*)g_h16)[(size_t)r1 * 64 + c2] = *(uint32_t*)&p;
            }
            if (r2 < Nn) {
                __half2 p = __floats2half2_rn(acc[t][nt][2] * dv2, acc[t][nt][3] * dv2);
                ((uint32_t*)g_h16)[(size_t)r2 * 64 + c2] = *(uint32_t*)&p;
            }
        }
    }
}

// ------- gather: warp-staged CSR (coalesced) + shfl broadcast, 4-deep rows -------
// agg[d] = dinv[d] * (h'[d] + sum_e h'[src_e]) + bias
__global__ __launch_bounds__(512) void k_gather(const float* __restrict__ bias, int bnidx) {
    __shared__ float ss[16 * 128];

    int tid = threadIdx.x;
    int wloc = tid >> 5;
    int lane = tid & 31;
    int wid = blockIdx.x * 16 + wloc;

    int beg = g_off[wid];
    int end = g_off[wid + 1];
    float dn = g_dinv[wid];

    const uint2* hv = (const uint2*)g_h16;
    uint2 hs = hv[(size_t)wid * 32 + lane];
    float2 f0 = __half22float2(*(__half2*)&hs.x);
    float2 f1 = __half22float2(*(__half2*)&hs.y);
    float4 acc = make_float4(f0.x, f0.y, f1.x, f1.y);
    float4 acc2 = make_float4(0.f, 0.f, 0.f, 0.f);

    const int* csr = g_csr;
    int e = beg;
    while (e < end) {
        int cnt = end - e;
        if (cnt > 32) cnt = 32;
        int myidx = (lane < cnt) ? csr[e + lane] : 0;   // one coalesced read / 32 edges
        int j = 0;
        for (; j + 4 <= cnt; j += 4) {
            int s0 = __shfl_sync(0xffffffffu, myidx, j);
            int s1 = __shfl_sync(0xffffffffu, myidx, j + 1);
            int s2 = __shfl_sync(0xffffffffu, myidx, j + 2);
            int s3 = __shfl_sync(0xffffffffu, myidx, j + 3);
            uint2 v0 = hv[(size_t)s0 * 32 + lane];
            uint2 v1 = hv[(size_t)s1 * 32 + lane];
            uint2 v2 = hv[(size_t)s2 * 32 + lane];
            uint2 v3 = hv[(size_t)s3 * 32 + lane];
            float2 a0 = __half22float2(*(__half2*)&v0.x), a1 = __half22float2(*(__half2*)&v0.y);
            float2 b0 = __half22float2(*(__half2*)&v1.x), b1 = __half22float2(*(__half2*)&v1.y);
            float2 d0 = __half22float2(*(__half2*)&v2.x), d1 = __half22float2(*(__half2*)&v2.y);
            float2 e0 = __half22float2(*(__half2*)&v3.x), e1 = __half22float2(*(__half2*)&v3.y);
            acc.x += a0.x + d0.x;  acc.y += a0.y + d0.y;
            acc.z += a1.x + d1.x;  acc.w += a1.y + d1.y;
            acc2.x += b0.x + e0.x; acc2.y += b0.y + e0.y;
            acc2.z += b1.x + e1.x; acc2.w += b1.y + e1.y;
        }
        for (; j < cnt; j++) {
            int s0 = __shfl_sync(0xffffffffu, myidx, j);
            uint2 v0 = hv[(size_t)s0 * 32 + lane];
            float2 a0 = __half22float2(*(__half2*)&v0.x);
            float2 a1 = __half22float2(*(__half2*)&v0.y);
            acc.x += a0.x; acc.y += a0.y; acc.z += a1.x; acc.w += a1.y;
        }
        e += cnt;
    }
    acc.x += acc2.x; acc.y += acc2.y; acc.z += acc2.z; acc.w += acc2.w;

    float4 b4 = ((const float4*)bias)[lane];
    acc.x = fmaf(acc.x, dn, b4.x);
    acc.y = fmaf(acc.y, dn, b4.y);
    acc.z = fmaf(acc.z, dn, b4.z);
    acc.w = fmaf(acc.w, dn, b4.w);
    ((float4*)g_agg)[(size_t)wid * 32 + lane] = acc;

    int base = wloc * 128 + lane * 4;
    ss[base + 0] = acc.x; ss[base + 1] = acc.y; ss[base + 2] = acc.z; ss[base + 3] = acc.w;
    __syncthreads();

    if (tid < 256) {
        int c = tid & 127;
        int part = tid >> 7;
        float r = 0.f;
        if (part == 0) {
#pragma unroll
            for (int w = 0; w < 16; w++) r += ss[w * 128 + c];
        } else {
#pragma unroll
            for (int w = 0; w < 16; w++) { float v = ss[w * 128 + c]; r = fmaf(v, v, r); }
        }
        atomicAdd(&g_z.bnsum[bnidx][blockIdx.x & (BN_REP - 1)][part * 128 + c], r);
    }
}

// ---------------- pooling with fused layer-3 BN finalize+apply ----------------
#define PCHUNK 128
__global__ void k_pool(const int* __restrict__ batch,
                       const float* __restrict__ gam, const float* __restrict__ bet) {
    int c = threadIdx.x;
    float s = 0.f, q = 0.f;
#pragma unroll
    for (int r = 0; r < BN_REP; r++) {
        s += g_z.bnsum[2][r][c];
        q += g_z.bnsum[2][r][128 + c];
    }
    float mean = s * (1.0f / (float)Nn);
    float var = q * (1.0f / (float)Nn) - mean * mean;
    float sc = gam[c] * rsqrtf(var + EPSf);
    float sh = bet[c] - mean * sc;

    int start = blockIdx.x * PCHUNK;
    if (start >= Nn) return;
    int end = min(start + PCHUNK, Nn);
    float acc = 0.f, ccnt = 0.f;
    int gp = batch[start];
    for (int n = start; n < end; n++) {
        int g = batch[n];
        if (g != gp) {
            atomicAdd(&g_z.xsum[gp * 128 + c], acc);
            if (c == 0) atomicAdd(&g_z.cnt[gp], ccnt);
            acc = 0.f; ccnt = 0.f; gp = g;
        }
        float a = g_agg[(size_t)n * 128 + c];
        float v = fmaxf(fmaf(a, sc, sh), 0.f) + g_act[(size_t)n * 128 + c];
        acc += v;
        ccnt += 1.f;
    }
    atomicAdd(&g_z.xsum[gp * 128 + c], acc);
    if (c == 0) atomicAdd(&g_z.cnt[gp], ccnt);
}

// ---------------- MLP head ----------------
__global__ void k_mlp(const float* __restrict__ Wm1, const float* __restrict__ bm1,
                      const float* __restrict__ Wm2, const float* __restrict__ bm2,
                      float* __restrict__ out) {
    __shared__ float zs[128], zm[128], hid[128];
    int g = blockIdx.x, c = threadIdx.x;
    float cnt = fmaxf(g_z.cnt[g], 1.0f);
    float xs = g_z.xsum[g * 128 + c];
    zs[c] = xs;
    zm[c] = xs / cnt;
    __syncthreads();
    float acc = bm1[c];
#pragma unroll 8
    for (int k = 0; k < 128; k++)
        acc += zs[k] * Wm1[k * 128 + c] + zm[k] * Wm1[(128 + k) * 128 + c];
    hid[c] = fmaxf(acc, 0.f) * Wm2[c];
    __syncthreads();
    for (int s = 64; s > 0; s >>= 1) {
        if (c < s) hid[c] += hid[c + s];
        __syncthreads();
    }
    if (c == 0) out[g] = hid[0] + bm2[0];
}

// ---------------- host ----------------
extern "C" void kernel_launch(void* const* d_in, const int* in_sizes, int n_in,
                              void* d_out, int out_size) {
    const float *x, *W1, *b1, *W2, *b2, *W3, *b3;
    const float *g1, *be1, *g2, *be2, *g3, *be3;
    const float *Wm1, *bm1, *Wm2, *bm2;
    const int *ei, *batch;

    if (in_sizes[1] == 2 * Ee) {
        x   = (const float*)d_in[0];
        ei  = (const int*)  d_in[1];
        batch = (const int*)d_in[2];
        W1 = (const float*)d_in[3];  b1 = (const float*)d_in[4];
        W2 = (const float*)d_in[5];  b2 = (const float*)d_in[6];
        W3 = (const float*)d_in[7];  b3 = (const float*)d_in[8];
        g1 = (const float*)d_in[9];  be1 = (const float*)d_in[10];
        g2 = (const float*)d_in[11]; be2 = (const float*)d_in[12];
        g3 = (const float*)d_in[13]; be3 = (const float*)d_in[14];
        Wm1 = (const float*)d_in[15]; bm1 = (const float*)d_in[16];
        Wm2 = (const float*)d_in[17]; bm2 = (const float*)d_in[18];
    } else {
        x   = (const float*)d_in[0];
        W1 = (const float*)d_in[1];  b1 = (const float*)d_in[2];
        g1 = (const float*)d_in[3];  be1 = (const float*)d_in[4];
        W2 = (const float*)d_in[5];  b2 = (const float*)d_in[6];
        g2 = (const float*)d_in[7];  be2 = (const float*)d_in[8];
        W3 = (const float*)d_in[9];  b3 = (const float*)d_in[10];
        g3 = (const float*)d_in[11]; be3 = (const float*)d_in[12];
        Wm1 = (const float*)d_in[13]; bm1 = (const float*)d_in[14];
        Wm2 = (const float*)d_in[15]; bm2 = (const float*)d_in[16];
        ei  = (const int*)d_in[17];
        batch = (const int*)d_in[18];
    }

    const int* src = ei;
    const int* dst = ei + Ee;
    float* out = (float*)d_out;

    static cudaStream_t s_side = nullptr;
    static cudaEvent_t s_e1 = nullptr, s_e2 = nullptr;
    if (!s_side) {
        cudaStreamCreateWithFlags(&s_side, cudaStreamNonBlocking);
        cudaEventCreateWithFlags(&s_e1, cudaEventDisableTiming);
        cudaEventCreateWithFlags(&s_e2, cudaEventDisableTiming);
    }

    cudaFuncSetAttribute(gemm_tc, cudaFuncAttributeMaxDynamicSharedMemorySize, SM_TOTAL);

    const int ZB = (Nn + 255) / 256;          // 391
    const int EB = (Ee + 255) / 256;          // 6250
    const int GATB = (Nn + 15) / 16;          // 6250 x 512
    const int POOLB = (Nn + PCHUNK - 1) / PCHUNK;  // 782

    void* zptr = nullptr;
    cudaGetSymbolAddress(&zptr, g_z);
    cudaMemsetAsync(zptr, 0, sizeof(ZBlob), 0);

    k_deg<<<EB, 256>>>(dst);
    cudaEventRecord(s_e1, 0);
    cudaStreamWaitEvent(s_side, s_e1, 0);

    k_prep<<<DINVB + 384, 128>>>(W1, W2, W3);
    k_scan1<<<NBLK, SCAN_BS, 0, s_side>>>();
    gemm_tc<<<TILES, 512, SM_TOTAL>>>(x, 0, 0, 0, nullptr, nullptr);
    k_scan2<<<1, 128, 0, s_side>>>();
    k_scan3<<<ZB, 256, 0, s_side>>>();
    k_fill<<<EB, 256, 0, s_side>>>(src, dst);
    cudaEventRecord(s_e2, s_side);
    cudaStreamWaitEvent(0, s_e2, 0);

    k_gather<<<GATB, 512>>>(b1, 0);

    gemm_tc<<<TILES, 512, SM_TOTAL>>>(nullptr, 1, 1, 0, g1, be1);
    k_gather<<<GATB, 512>>>(b2, 1);

    gemm_tc<<<TILES, 512, SM_TOTAL>>>(nullptr, 2, 2, 1, g2, be2);
    k_gather<<<GATB, 512>>>(b3, 2);

    k_pool<<<POOLB, 128>>>(batch, g3, be3);
    k_mlp<<<Gg, 128>>>(Wm1, bm1, Wm2, bm2, out);
}